// round 1
// baseline (speedup 1.0000x reference)
#include <cuda_runtime.h>

#define N_ATOMS 1024
#define TPB 256
#define MAX_PARTIALS 256

__device__ float g_partials[MAX_PARTIALS];

__global__ void __launch_bounds__(TPB, 2)
collapse_pair_kernel(const float* __restrict__ coords)
{
    __shared__ float xs[N_ATOMS];
    __shared__ float ys[N_ATOMS];
    __shared__ float zs[N_ATOMS];

    const int b = blockIdx.y;
    const float* cb = coords + (size_t)b * (3 * N_ATOMS);

    // Load batch's atoms into SoA shared memory (12 KB, L2-resident source)
    for (int n = threadIdx.x; n < N_ATOMS; n += TPB) {
        float x = cb[3 * n + 0];
        float y = cb[3 * n + 1];
        float z = cb[3 * n + 2];
        xs[n] = x; ys[n] = y; zs[n] = z;
    }
    __syncthreads();

    float acc = 0.0f;

    // Balanced triangular split: this thread owns rows i1 and (N-1-i1).
    // Work = (N-1-i1) + (N-1-i2) = N-1 = 1023 iterations, identical for all threads.
    const int i1 = blockIdx.x * TPB + threadIdx.x;   // [0, 512)
    const int i2 = (N_ATOMS - 1) - i1;               // [512, 1024)

    {
        const float xi = xs[i1], yi = ys[i1], zi = zs[i1];
        #pragma unroll 4
        for (int j = i1 + 1; j < N_ATOMS; ++j) {
            float dx = xi - xs[j];
            float dy = yi - ys[j];
            float dz = zi - zs[j];
            float d2 = fmaf(dx, dx, fmaf(dy, dy, dz * dz));
            if (d2 < 8.41f) {                       // 2.9^2 gate: sqrt path is rare (~0.8%)
                float v = 2.9f - sqrtf(d2 + 1e-8f);
                v = fmaxf(v, 0.0f);
                acc = fmaf(v, v, acc);
            }
        }
    }
    {
        const float xi = xs[i2], yi = ys[i2], zi = zs[i2];
        #pragma unroll 4
        for (int j = i2 + 1; j < N_ATOMS; ++j) {
            float dx = xi - xs[j];
            float dy = yi - ys[j];
            float dz = zi - zs[j];
            float d2 = fmaf(dx, dx, fmaf(dy, dy, dz * dz));
            if (d2 < 8.41f) {
                float v = 2.9f - sqrtf(d2 + 1e-8f);
                v = fmaxf(v, 0.0f);
                acc = fmaf(v, v, acc);
            }
        }
    }

    // Block reduction: warp shuffle, then cross-warp via shared
    #pragma unroll
    for (int o = 16; o > 0; o >>= 1)
        acc += __shfl_down_sync(0xFFFFFFFFu, acc, o);

    __shared__ float wsum[TPB / 32];
    const int lane = threadIdx.x & 31;
    const int wid  = threadIdx.x >> 5;
    if (lane == 0) wsum[wid] = acc;
    __syncthreads();

    if (threadIdx.x == 0) {
        float s = 0.0f;
        #pragma unroll
        for (int w = 0; w < TPB / 32; ++w) s += wsum[w];
        g_partials[blockIdx.y * gridDim.x + blockIdx.x] = s;
    }
}

__global__ void collapse_reduce_kernel(float* __restrict__ out, int n_partials, float inv_b)
{
    // Single block of 128 threads reduces up to MAX_PARTIALS partials.
    float v = 0.0f;
    for (int i = threadIdx.x; i < n_partials; i += 128)
        v += g_partials[i];

    #pragma unroll
    for (int o = 16; o > 0; o >>= 1)
        v += __shfl_down_sync(0xFFFFFFFFu, v, o);

    __shared__ float wsum[4];
    const int lane = threadIdx.x & 31;
    const int wid  = threadIdx.x >> 5;
    if (lane == 0) wsum[wid] = v;
    __syncthreads();

    if (threadIdx.x == 0) {
        float s = wsum[0] + wsum[1] + wsum[2] + wsum[3];
        out[0] = s * inv_b;   // LOSS_WEIGHT(=1) * total / B
    }
}

extern "C" void kernel_launch(void* const* d_in, const int* in_sizes, int n_in,
                              void* d_out, int out_size)
{
    const float* coords = (const float*)d_in[0];
    const int B = in_sizes[0] / (3 * N_ATOMS);   // 64 for this problem

    dim3 grid(N_ATOMS / (2 * TPB), B);           // (2, 64) = 128 CTAs
    collapse_pair_kernel<<<grid, TPB>>>(coords);

    collapse_reduce_kernel<<<1, 128>>>((float*)d_out, B * (N_ATOMS / (2 * TPB)), 1.0f / (float)B);
}

// round 2
// speedup vs baseline: 2.1067x; 2.1067x over previous
#include <cuda_runtime.h>

#define N_ATOMS 1024
#define TPB 128
#define GRID_X 4            // GRID_X * TPB == N_ATOMS/2
#define MAX_PARTIALS 1024

__device__ float g_partials[MAX_PARTIALS];
__device__ unsigned int g_count = 0;

__device__ __forceinline__ float fsqrt_approx(float x) {
    float r;
    asm("sqrt.approx.f32 %0, %1;" : "=f"(r) : "f"(x));
    return r;
}

__device__ __forceinline__ float row_loss(const float4* __restrict__ atoms,
                                          int i, int jend)
{
    const float4 ai = atoms[i];
    const float xi = ai.x, yi = ai.y, zi = ai.z;
    float acc0 = 0.0f, acc1 = 0.0f;

    int j = i + 1;
    #pragma unroll 8
    for (; j < jend; ++j) {
        float4 aj = atoms[j];
        float dx = xi - aj.x;
        float dy = yi - aj.y;
        float dz = zi - aj.z;
        float d2 = fmaf(dx, dx, fmaf(dy, dy, dz * dz));
        float d  = fsqrt_approx(d2 + 1e-8f);
        float v  = fmaxf(2.9f - d, 0.0f);
        if (j & 1) acc0 = fmaf(v, v, acc0);
        else       acc1 = fmaf(v, v, acc1);
    }
    return acc0 + acc1;
}

__global__ void __launch_bounds__(TPB)
collapse_fused_kernel(const float* __restrict__ coords,
                      float* __restrict__ out,
                      int nblocks, float inv_b)
{
    __shared__ float4 atoms[N_ATOMS];      // 16 KB, SoA-per-atom (x,y,z,pad)
    __shared__ float  wsum[TPB / 32];
    __shared__ bool   isLast;

    const int tid = threadIdx.x;
    const int b   = blockIdx.y;
    const float* cb = coords + (size_t)b * (3 * N_ATOMS);

    for (int n = tid; n < N_ATOMS; n += TPB) {
        float4 a;
        a.x = cb[3 * n + 0];
        a.y = cb[3 * n + 1];
        a.z = cb[3 * n + 2];
        a.w = 0.0f;
        atoms[n] = a;
    }
    __syncthreads();

    // Balanced triangular split: thread owns rows i1 in [0,512) and 1023-i1.
    // Total inner-loop trip count = 1023 for every thread.
    const int i1 = blockIdx.x * TPB + tid;
    const int i2 = (N_ATOMS - 1) - i1;

    float acc = row_loss(atoms, i1, N_ATOMS)
              + row_loss(atoms, i2, N_ATOMS);

    // Intra-block reduction
    #pragma unroll
    for (int o = 16; o > 0; o >>= 1)
        acc += __shfl_down_sync(0xFFFFFFFFu, acc, o);
    const int lane = tid & 31;
    const int wid  = tid >> 5;
    if (lane == 0) wsum[wid] = acc;
    __syncthreads();

    if (tid == 0) {
        float s = 0.0f;
        #pragma unroll
        for (int w = 0; w < TPB / 32; ++w) s += wsum[w];
        g_partials[blockIdx.y * gridDim.x + blockIdx.x] = s;
        __threadfence();                               // publish partial
        unsigned int c = atomicAdd(&g_count, 1u);
        isLast = (c == (unsigned int)(nblocks - 1));
    }
    __syncthreads();

    // Last CTA to finish reduces all partials in a FIXED order (deterministic).
    if (isLast) {
        __threadfence();                               // acquire partials
        if (tid < 32) {
            float s = 0.0f;
            for (int k = tid; k < nblocks; k += 32)
                s += g_partials[k];
            #pragma unroll
            for (int o = 16; o > 0; o >>= 1)
                s += __shfl_down_sync(0xFFFFFFFFu, s, o);
            if (tid == 0) {
                out[0] = s * inv_b;
                g_count = 0;                           // reset for graph replay
            }
        }
    }
}

extern "C" void kernel_launch(void* const* d_in, const int* in_sizes, int n_in,
                              void* d_out, int out_size)
{
    const float* coords = (const float*)d_in[0];
    const int B = in_sizes[0] / (3 * N_ATOMS);

    dim3 grid(GRID_X, B);
    const int nblocks = GRID_X * B;
    collapse_fused_kernel<<<grid, TPB>>>(coords, (float*)d_out,
                                         nblocks, 1.0f / (float)B);
}

// round 3
// speedup vs baseline: 3.3626x; 1.5962x over previous
#include <cuda_runtime.h>

#define N_ATOMS   1024
#define TPB       256          // threads per CTA; each thread owns 4 rows
#define NSEG      8            // k-segments per batch; 512 k-steps / 8 = 64 per CTA
#define KSEG      64
#define NBLOCKS   (NSEG * 64)  // grid for B=64

__device__ float g_partials[1024];
__device__ unsigned int g_count = 0;

__device__ __forceinline__ float fsqrt_approx(float x) {
    float r;
    asm("sqrt.approx.f32 %0, %1;" : "=f"(r) : "f"(x));
    return r;
}

// padded smem index: 16B pad every 8 atoms -> conflict-free LDS.128 at lane stride 4 atoms
__device__ __forceinline__ int sidx(int n) { return n + (n >> 3); }

// one pair: rc = (-2xi, -2yi, -2zi, ri), W = (xj, yj, zj, rj)
#define PAIR(RC, W, ACC) do {                                                   \
    float _p  = fmaf((RC).x, (W).x, fmaf((RC).y, (W).y, fmaf((RC).z, (W).z, (RC).w))); \
    float _d2 = fmaxf(_p + (W).w, 0.0f);                                        \
    float _d  = fsqrt_approx(_d2);                                              \
    float _v  = fmaxf(2.9f - _d, 0.0f);                                         \
    (ACC) = fmaf(_v, _v, (ACC));                                                \
} while (0)

// one k-step: 4 pairs against rotating window, then refill slot W0
#define STEP(W0, W1, W2, W3) do {                                               \
    PAIR(c0, W0, acc0); PAIR(c1, W1, acc1);                                     \
    PAIR(c2, W2, acc0); PAIR(c3, W3, acc1);                                     \
    n = (n + 1) & (N_ATOMS - 1);                                                \
    W0 = atoms_s[sidx(n)];                                                      \
} while (0)

__global__ void __launch_bounds__(TPB)
collapse_kernel(const float* __restrict__ coords,
                float* __restrict__ out,
                int nblocks, float inv_b)
{
    __shared__ float4 atoms_s[N_ATOMS + N_ATOMS / 8];   // 1152 * 16B = 18 KB
    __shared__ float  wsum[TPB / 32];
    __shared__ bool   isLast;

    const int tid = threadIdx.x;
    const int seg = blockIdx.x;          // k-segment [0, NSEG)
    const int b   = blockIdx.y;          // batch

    // ---- fill smem: (x, y, z, r) per atom, padded layout ----
    {
        const float4* cb4 = (const float4*)(coords + (size_t)b * (3 * N_ATOMS));
        float4 f0 = cb4[3 * tid + 0];
        float4 f1 = cb4[3 * tid + 1];
        float4 f2 = cb4[3 * tid + 2];
        float4 a0 = make_float4(f0.x, f0.y, f0.z, 0.f);
        float4 a1 = make_float4(f0.w, f1.x, f1.y, 0.f);
        float4 a2 = make_float4(f1.z, f1.w, f2.x, 0.f);
        float4 a3 = make_float4(f2.y, f2.z, f2.w, 0.f);
        a0.w = fmaf(a0.x, a0.x, fmaf(a0.y, a0.y, a0.z * a0.z));
        a1.w = fmaf(a1.x, a1.x, fmaf(a1.y, a1.y, a1.z * a1.z));
        a2.w = fmaf(a2.x, a2.x, fmaf(a2.y, a2.y, a2.z * a2.z));
        a3.w = fmaf(a3.x, a3.x, fmaf(a3.y, a3.y, a3.z * a3.z));
        atoms_s[sidx(4 * tid + 0)] = a0;
        atoms_s[sidx(4 * tid + 1)] = a1;
        atoms_s[sidx(4 * tid + 2)] = a2;
        atoms_s[sidx(4 * tid + 3)] = a3;
    }
    __syncthreads();

    // ---- per-thread row constants: rows i0..i0+3 ----
    const int i0 = 4 * tid;
    float4 c0, c1, c2, c3;
    {
        float4 a;
        a = atoms_s[sidx(i0 + 0)]; c0 = make_float4(-2.f * a.x, -2.f * a.y, -2.f * a.z, a.w);
        a = atoms_s[sidx(i0 + 1)]; c1 = make_float4(-2.f * a.x, -2.f * a.y, -2.f * a.z, a.w);
        a = atoms_s[sidx(i0 + 2)]; c2 = make_float4(-2.f * a.x, -2.f * a.y, -2.f * a.z, a.w);
        a = atoms_s[sidx(i0 + 3)]; c3 = make_float4(-2.f * a.x, -2.f * a.y, -2.f * a.z, a.w);
    }

    // ---- prime sliding window for k0 = seg*KSEG + 1 ----
    const int k0 = seg * KSEG + 1;
    float4 wA = atoms_s[sidx((i0 + k0 + 0) & (N_ATOMS - 1))];
    float4 wB = atoms_s[sidx((i0 + k0 + 1) & (N_ATOMS - 1))];
    float4 wC = atoms_s[sidx((i0 + k0 + 2) & (N_ATOMS - 1))];
    float4 wD = atoms_s[sidx((i0 + k0 + 3) & (N_ATOMS - 1))];
    int n = (i0 + k0 + 3) & (N_ATOMS - 1);

    float acc0 = 0.0f, acc1 = 0.0f;

    // ---- main loop: KSEG k-steps, 4 pairs each, window rotates by rename ----
    #pragma unroll 2
    for (int kb = 0; kb < KSEG / 4; ++kb) {
        STEP(wA, wB, wC, wD);
        STEP(wB, wC, wD, wA);
        STEP(wC, wD, wA, wB);
        STEP(wD, wA, wB, wC);
    }

    // ---- k=512 pairs were counted twice chip-wide: subtract half (last segment only) ----
    if (seg == NSEG - 1) {
        #pragma unroll
        for (int t = 0; t < 4; ++t) {
            const float4 rc = (t == 0) ? c0 : (t == 1) ? c1 : (t == 2) ? c2 : c3;
            int j = (i0 + t + 512) & (N_ATOMS - 1);
            float4 W = atoms_s[sidx(j)];
            float p  = fmaf(rc.x, W.x, fmaf(rc.y, W.y, fmaf(rc.z, W.z, rc.w)));
            float d2 = fmaxf(p + W.w, 0.0f);
            float d  = fsqrt_approx(d2);
            float v  = fmaxf(2.9f - d, 0.0f);
            acc0 = fmaf(v, -0.5f * v, acc0);
        }
    }

    float acc = acc0 + acc1;

    // ---- intra-CTA reduction ----
    #pragma unroll
    for (int o = 16; o > 0; o >>= 1)
        acc += __shfl_down_sync(0xFFFFFFFFu, acc, o);
    const int lane = tid & 31, wid = tid >> 5;
    if (lane == 0) wsum[wid] = acc;
    __syncthreads();

    if (tid == 0) {
        float s = 0.0f;
        #pragma unroll
        for (int w = 0; w < TPB / 32; ++w) s += wsum[w];
        g_partials[blockIdx.y * gridDim.x + blockIdx.x] = s;
        __threadfence();
        unsigned int c = atomicAdd(&g_count, 1u);
        isLast = (c == (unsigned int)(nblocks - 1));
    }
    __syncthreads();

    // ---- last CTA reduces all partials in fixed order (deterministic) ----
    if (isLast) {
        __threadfence();
        if (tid < 32) {
            float s = 0.0f;
            for (int k = tid; k < nblocks; k += 32)
                s += g_partials[k];
            #pragma unroll
            for (int o = 16; o > 0; o >>= 1)
                s += __shfl_down_sync(0xFFFFFFFFu, s, o);
            if (tid == 0) {
                out[0] = s * inv_b;
                g_count = 0;     // reset for graph replay
            }
        }
    }
}

extern "C" void kernel_launch(void* const* d_in, const int* in_sizes, int n_in,
                              void* d_out, int out_size)
{
    const float* coords = (const float*)d_in[0];
    const int B = in_sizes[0] / (3 * N_ATOMS);   // 64

    dim3 grid(NSEG, B);
    const int nblocks = NSEG * B;
    collapse_kernel<<<grid, TPB>>>(coords, (float*)d_out, nblocks, 1.0f / (float)B);
}

// round 5
// speedup vs baseline: 3.7374x; 1.1115x over previous
#include <cuda_runtime.h>

#define N_ATOMS 1024
#define NPAIRS  512          // packed column-pairs per copy
#define TPB     256
#define NSEG    8            // k-segments; 256 packed k-steps total
#define STEPS   (256 / NSEG) // 32 packed k-steps per CTA

__device__ float g_partials[1024];
__device__ unsigned int g_count = 0;

typedef unsigned long long u64;

__device__ __forceinline__ u64 fma2(u64 a, u64 b, u64 c) {
    u64 d; asm("fma.rn.f32x2 %0, %1, %2, %3;" : "=l"(d) : "l"(a), "l"(b), "l"(c)); return d;
}
__device__ __forceinline__ u64 add2(u64 a, u64 b) {
    u64 d; asm("add.rn.f32x2 %0, %1, %2;" : "=l"(d) : "l"(a), "l"(b)); return d;
}
__device__ __forceinline__ u64 pack2(float lo, float hi) {
    u64 d; asm("mov.b64 %0, {%1, %2};" : "=l"(d) : "f"(lo), "f"(hi)); return d;
}
__device__ __forceinline__ float fsqrt_approx(float x) {
    float r; asm("sqrt.approx.f32 %0, %1;" : "=f"(r) : "f"(x)); return r;
}

// padded packed-slot index in float4 units: slot c -> 2c + c/4 (16B pad per 4 slots)
#define PSLOT(c) (2 * (c) + ((c) >> 2))

// one packed op = 2 pairs: row consts (X=-2xi bcast, Y, Z, R=ri+1e-8 bcast)
// vs slot regs (sx=(xj0,xj1), sy, sz, sr=(rj0,rj1))
#define PAIR2(X, Y, Z, R, sx, sy, sz, sr, ACC) do {                          \
    u64 _t = fma2(X, sx, fma2(Y, sy, fma2(Z, sz, sr)));                      \
    u64 _d2 = add2(_t, R);                                                   \
    float _a, _b;                                                            \
    asm("mov.b64 {%0, %1}, %2;" : "=f"(_a), "=f"(_b) : "l"(_d2));            \
    float _v0 = fmaxf(2.9f - fsqrt_approx(_a), 0.0f);                        \
    float _v1 = fmaxf(2.9f - fsqrt_approx(_b), 0.0f);                        \
    ACC = fmaf(_v0, _v0, ACC);                                               \
    ACC = fmaf(_v1, _v1, ACC);                                               \
} while (0)

#define LOAD_SLOT(s, cidx) do {                                              \
    int _f4 = PSLOT(cidx);                                                   \
    const ulonglong2* _p = reinterpret_cast<const ulonglong2*>(cp + _f4);    \
    ulonglong2 _u = _p[0];                                                   \
    ulonglong2 _w = _p[1];                                                   \
    s##x = _u.x; s##y = _u.y; s##z = _w.x; s##r = _w.y;                      \
} while (0)

// one k-step: 4 rows x 2 packed pairs against rotating window; refill slot a
#define STEP4(a, b, c, d) do {                                               \
    PAIR2(X20, Y20, Z20, R20, a##x, a##y, a##z, a##r, acc0);                 \
    PAIR2(X21, Y21, Z21, R21, b##x, b##y, b##z, b##r, acc1);                 \
    PAIR2(X22, Y22, Z22, R22, c##x, c##y, c##z, c##r, acc2);                 \
    PAIR2(X23, Y23, Z23, R23, d##x, d##y, d##z, d##r, acc3);                 \
    n = (n + 1) & (NPAIRS - 1);                                              \
    LOAD_SLOT(a, n);                                                         \
} while (0)

__global__ void __launch_bounds__(TPB)
collapse_kernel(const float* __restrict__ coords,
                float* __restrict__ out,
                int nblocks, float inv_b)
{
    // copyA packs atoms (2c, 2c+1); copyB packs (2c+1, 2c+2 mod N). ~18 KB each.
    __shared__ float4 cpyA[2 * NPAIRS + NPAIRS / 4];
    __shared__ float4 cpyB[2 * NPAIRS + NPAIRS / 4];
    __shared__ float  wsum[TPB / 32];
    __shared__ bool   isLast;

    const int t   = threadIdx.x;
    const int seg = blockIdx.x;
    const int b   = blockIdx.y;

    // ---- prologue: load own atoms 4t..4t+3, compute r, build copyA ----
    float ax0,ax1,ax2,ax3, ay0,ay1,ay2,ay3, az0,az1,az2,az3, ar0,ar1,ar2,ar3;
    {
        const float4* cb4 = (const float4*)(coords + (size_t)b * (3 * N_ATOMS));
        float4 f0 = cb4[3 * t + 0];
        float4 f1 = cb4[3 * t + 1];
        float4 f2 = cb4[3 * t + 2];
        ax0 = f0.x; ay0 = f0.y; az0 = f0.z;
        ax1 = f0.w; ay1 = f1.x; az1 = f1.y;
        ax2 = f1.z; ay2 = f1.w; az2 = f2.x;
        ax3 = f2.y; ay3 = f2.z; az3 = f2.w;
        ar0 = fmaf(ax0, ax0, fmaf(ay0, ay0, az0 * az0));
        ar1 = fmaf(ax1, ax1, fmaf(ay1, ay1, az1 * az1));
        ar2 = fmaf(ax2, ax2, fmaf(ay2, ay2, az2 * az2));
        ar3 = fmaf(ax3, ax3, fmaf(ay3, ay3, az3 * az3));
        cpyA[PSLOT(2 * t)    ] = make_float4(ax0, ax1, ay0, ay1);
        cpyA[PSLOT(2 * t) + 1] = make_float4(az0, az1, ar0, ar1);
        cpyA[PSLOT(2 * t + 1)    ] = make_float4(ax2, ax3, ay2, ay3);
        cpyA[PSLOT(2 * t + 1) + 1] = make_float4(az2, az3, ar2, ar3);
    }
    __syncthreads();

    // ---- build copyB (needs atom 4t+4 -> read from copyA) ----
    {
        int cn = (2 * t + 2) & (NPAIRS - 1);
        float4 n1 = cpyA[PSLOT(cn)];
        float4 n2 = cpyA[PSLOT(cn) + 1];
        float nx = n1.x, ny = n1.z, nz = n2.x, nr = n2.z;   // low half = atom 4t+4
        cpyB[PSLOT(2 * t)    ] = make_float4(ax1, ax2, ay1, ay2);
        cpyB[PSLOT(2 * t) + 1] = make_float4(az1, az2, ar1, ar2);
        cpyB[PSLOT(2 * t + 1)    ] = make_float4(ax3, nx, ay3, ny);
        cpyB[PSLOT(2 * t + 1) + 1] = make_float4(az3, nz, ar3, nr);
    }
    __syncthreads();

    // ---- row assignment: m=t&127, p=t>>7; rows i0+2r, r=0..3, i0=8m+p ----
    const int m  = t & 127;
    const int p  = t >> 7;                 // 0: even rows (use copyB), 1: odd rows (use copyA)
    const int i0 = 8 * m + p;
    const float4* cp = p ? cpyA : cpyB;

    // ---- row constants: read own rows from copyA ----
    u64 X20,Y20,Z20,R20, X21,Y21,Z21,R21, X22,Y22,Z22,R22, X23,Y23,Z23,R23;
    {
        #define ROWCONST(r, X, Y, Z, R) do {                                 \
            int _i = i0 + 2 * (r);                                           \
            int _c = _i >> 1;                                                \
            float4 _q1 = cpyA[PSLOT(_c)];                                    \
            float4 _q2 = cpyA[PSLOT(_c) + 1];                                \
            float _xi = p ? _q1.y : _q1.x;                                   \
            float _yi = p ? _q1.w : _q1.z;                                   \
            float _zi = p ? _q2.y : _q2.x;                                   \
            float _ri = (p ? _q2.w : _q2.z) + 1e-8f;                         \
            X = pack2(-2.f * _xi, -2.f * _xi);                               \
            Y = pack2(-2.f * _yi, -2.f * _yi);                               \
            Z = pack2(-2.f * _zi, -2.f * _zi);                               \
            R = pack2(_ri, _ri);                                             \
        } while (0)
        ROWCONST(0, X20, Y20, Z20, R20);
        ROWCONST(1, X21, Y21, Z21, R21);
        ROWCONST(2, X22, Y22, Z22, R22);
        ROWCONST(3, X23, Y23, Z23, R23);
    }

    // ---- prime window: k0 = first odd k of this segment ----
    const int k0  = 1 + 2 * seg * STEPS;
    const int cb0 = ((i0 + k0) >> 1) & (NPAIRS - 1);
    u64 Ax,Ay,Az,Ar, Bx,By,Bz,Br, Cx,Cy,Cz,Cr, Dx,Dy,Dz,Dr;
    LOAD_SLOT(A, cb0);
    LOAD_SLOT(B, (cb0 + 1) & (NPAIRS - 1));
    LOAD_SLOT(C, (cb0 + 2) & (NPAIRS - 1));
    LOAD_SLOT(D, (cb0 + 3) & (NPAIRS - 1));
    int n = (cb0 + 3) & (NPAIRS - 1);

    float acc0 = 0.f, acc1 = 0.f, acc2 = 0.f, acc3 = 0.f;

    // ---- main loop: STEPS packed k-steps (4 rows x 2 pairs each) ----
    for (int it = 0; it < STEPS / 4; ++it) {
        STEP4(A, B, C, D);
        STEP4(B, C, D, A);
        STEP4(C, D, A, B);
        STEP4(D, A, B, C);
    }

    // ---- k=512 double-count correction (last segment only) ----
    if (seg == NSEG - 1) {
        #pragma unroll
        for (int r = 0; r < 4; ++r) {
            int i = i0 + 2 * r;
            int j = (i + 512) & (N_ATOMS - 1);
            int c = j >> 1;
            float4 q1 = cpyA[PSLOT(c)];
            float4 q2 = cpyA[PSLOT(c) + 1];
            float xj = p ? q1.y : q1.x;
            float yj = p ? q1.w : q1.z;
            float zj = p ? q2.y : q2.x;
            float rj = p ? q2.w : q2.z;
            u64 X = (r==0)?X20:(r==1)?X21:(r==2)?X22:X23;
            u64 Y = (r==0)?Y20:(r==1)?Y21:(r==2)?Y22:Y23;
            u64 Z = (r==0)?Z20:(r==1)?Z21:(r==2)?Z22:Z23;
            u64 R = (r==0)?R20:(r==1)?R21:(r==2)?R22:R23;
            float m2x, m2y, m2z, ri, du;
            asm("mov.b64 {%0, %1}, %2;" : "=f"(m2x), "=f"(du) : "l"(X));
            asm("mov.b64 {%0, %1}, %2;" : "=f"(m2y), "=f"(du) : "l"(Y));
            asm("mov.b64 {%0, %1}, %2;" : "=f"(m2z), "=f"(du) : "l"(Z));
            asm("mov.b64 {%0, %1}, %2;" : "=f"(ri),  "=f"(du) : "l"(R));
            float tt = fmaf(m2x, xj, fmaf(m2y, yj, fmaf(m2z, zj, rj)));
            float d2 = tt + ri;
            float v  = fmaxf(2.9f - fsqrt_approx(d2), 0.0f);
            acc0 = fmaf(v, -0.5f * v, acc0);
        }
    }

    float acc = (acc0 + acc1) + (acc2 + acc3);

    // ---- intra-CTA reduction ----
    #pragma unroll
    for (int o = 16; o > 0; o >>= 1)
        acc += __shfl_down_sync(0xFFFFFFFFu, acc, o);
    const int lane = t & 31, wid = t >> 5;
    if (lane == 0) wsum[wid] = acc;
    __syncthreads();

    if (t == 0) {
        float s = 0.f;
        #pragma unroll
        for (int w = 0; w < TPB / 32; ++w) s += wsum[w];
        g_partials[blockIdx.y * gridDim.x + blockIdx.x] = s;
        __threadfence();
        unsigned int c = atomicAdd(&g_count, 1u);
        isLast = (c == (unsigned int)(nblocks - 1));
    }
    __syncthreads();

    // ---- last CTA: fixed-order deterministic final reduce ----
    if (isLast) {
        __threadfence();
        if (t < 32) {
            float s = 0.f;
            for (int k = t; k < nblocks; k += 32)
                s += g_partials[k];
            #pragma unroll
            for (int o = 16; o > 0; o >>= 1)
                s += __shfl_down_sync(0xFFFFFFFFu, s, o);
            if (t == 0) {
                out[0] = s * inv_b;
                g_count = 0;   // reset for graph replay
            }
        }
    }
}

extern "C" void kernel_launch(void* const* d_in, const int* in_sizes, int n_in,
                              void* d_out, int out_size)
{
    const float* coords = (const float*)d_in[0];
    const int B = in_sizes[0] / (3 * N_ATOMS);   // 64

    dim3 grid(NSEG, B);
    const int nblocks = NSEG * B;
    collapse_kernel<<<grid, TPB>>>(coords, (float*)d_out, nblocks, 1.0f / (float)B);
}